// round 5
// baseline (speedup 1.0000x reference)
#include <cuda_runtime.h>
#include <cuda_fp16.h>
#include <cstdint>

// Problem constants
#define MM 8192
#define NN 8192
#define KK 4096
#define TM 128
#define TN 128
#define KS 64               // K elems per pipeline stage (128B rows)
#define STAGES 3
#define K_ITERS (KK / KS)   // 64

// Static scratch (allocation-free rule: __device__ globals): 64 MB + 64 MB
__device__ __half g_Ah[(size_t)MM * KK];
__device__ __half g_Wh[(size_t)NN * KK];

// ---------------------------------------------------------------------------
// Prep kernel 1: A (fp32, MxK) -> Ah (fp16, MxK). 8 elems/thread.
// ---------------------------------------------------------------------------
__global__ void prep_a_kernel(const float* __restrict__ A, __half* __restrict__ Ah) {
    size_t base = ((size_t)blockIdx.x * blockDim.x + threadIdx.x) * 8;
    float4 v0 = *reinterpret_cast<const float4*>(A + base);
    float4 v1 = *reinterpret_cast<const float4*>(A + base + 4);
    union { __half h[8]; uint4 u; } out;
    out.h[0] = __float2half(v0.x); out.h[1] = __float2half(v0.y);
    out.h[2] = __float2half(v0.z); out.h[3] = __float2half(v0.w);
    out.h[4] = __float2half(v1.x); out.h[5] = __float2half(v1.y);
    out.h[6] = __float2half(v1.z); out.h[7] = __float2half(v1.w);
    *reinterpret_cast<uint4*>(Ah + base) = out.u;
}

// ---------------------------------------------------------------------------
// Prep kernel 2: dequant int4 -> Wh (fp16, N x K), N-major rows.
// One thread = one n column x 64 k (8 packed words, one scale group).
// ---------------------------------------------------------------------------
__global__ void prep_w_kernel(const int* __restrict__ Bp, const float* __restrict__ s,
                              __half* __restrict__ Wh) {
    int n   = blockIdx.x * 256 + threadIdx.x;
    int kp0 = blockIdx.y * 8;                         // 8 packed rows = 64 k
    float sv = s[(size_t)(kp0 >> 4) * NN + n];        // group = kp/16
    __half* dst = Wh + (size_t)n * KK + kp0 * 8;
#pragma unroll
    for (int r = 0; r < 8; r++) {
        int packed = Bp[(size_t)(kp0 + r) * NN + n];
        union { __half h[8]; uint4 u; } out;
#pragma unroll
        for (int j = 0; j < 8; j++) {
            int q = (packed >> (4 * j)) & 0xF;
            out.h[j] = __float2half((float)(q - 8) * sv);
        }
        *reinterpret_cast<uint4*>(dst + r * 8) = out.u;
    }
}

// ---------------------------------------------------------------------------
// GEMM: C[M,N] = Ah @ Wh^T (fp16 in, f32 acc)
// CTA 128x128, 128 threads (4 warps, 2m x 2n, warp tile 64x64), occupancy 2.
// 3-stage cp.async pipeline, KS=64; chunk swizzle c^(row&7).
// ---------------------------------------------------------------------------
#define A_STAGE_BYTES 16384              // 128 x 64 x 2
#define B_STAGE_BYTES 16384              // 128 x 64 x 2
#define SMEM_BYTES (STAGES * (A_STAGE_BYTES + B_STAGE_BYTES))   // 98304

__device__ __forceinline__ uint32_t smem_u32(const void* p) {
    uint32_t a;
    asm("{ .reg .u64 t; cvta.to.shared.u64 t, %1; cvt.u32.u64 %0, t; }" : "=r"(a) : "l"(p));
    return a;
}

#define CP_ASYNC16(smem, gmem) \
    asm volatile("cp.async.cg.shared.global [%0], [%1], 16;" :: "r"(smem), "l"(gmem))
#define CP_COMMIT() asm volatile("cp.async.commit_group;" ::: "memory")
#define CP_WAIT1()  asm volatile("cp.async.wait_group 1;" ::: "memory")

#define LDSM_X4(r, addr) \
    asm volatile("ldmatrix.sync.aligned.m8n8.x4.shared.b16 {%0,%1,%2,%3}, [%4];" \
        : "=r"((r)[0]), "=r"((r)[1]), "=r"((r)[2]), "=r"((r)[3]) : "r"(addr))

#define MMA16816(d, a, b0, b1) \
    asm volatile("mma.sync.aligned.m16n8k16.row.col.f32.f16.f16.f32 " \
        "{%0,%1,%2,%3}, {%4,%5,%6,%7}, {%8,%9}, {%0,%1,%2,%3};" \
        : "+f"((d)[0]), "+f"((d)[1]), "+f"((d)[2]), "+f"((d)[3]) \
        : "r"((a)[0]), "r"((a)[1]), "r"((a)[2]), "r"((a)[3]), "r"(b0), "r"(b1))

__global__ __launch_bounds__(128, 2) void gemm_kernel(
    const __half* __restrict__ gA,
    const __half* __restrict__ gB,
    float* __restrict__ C)
{
    extern __shared__ char smem[];
    const uint32_t sbase = smem_u32(smem);
    const int tid = threadIdx.x, wid = tid >> 5, lid = tid & 31;

    // CTA swizzle: 8-wide m-bands sweeping n (L2 reuse: 8MB A band resident)
    const int TILES_N = NN / TN;        // 64
    const int GW = 8;
    int bid  = blockIdx.x;
    int band = bid / (GW * TILES_N);
    int rem  = bid % (GW * TILES_N);
    const int m0 = (band * GW + (rem % GW)) * TM;
    const int n0 = (rem / GW) * TN;

    const int warpM = (wid & 1) * 64;   // 2 m-warps
    const int warpN = (wid >> 1) * 64;  // 2 n-warps

    auto stage_load = [&](int st, int it) {
        const int k0 = it * KS;
        const uint32_t sa = sbase + st * A_STAGE_BYTES;
        const uint32_t sb = sbase + STAGES * A_STAGE_BYTES + st * B_STAGE_BYTES;
        const int c = tid & 7;          // constant across r (128 ≡ 0 mod 8)
#pragma unroll
        for (int r = 0; r < 8; r++) {                // A: 1024 chunks / 128 thr
            int row = (tid + r * 128) >> 3;
            uint32_t soff = row * 128 + ((c ^ (row & 7)) << 4);
            CP_ASYNC16(sa + soff, gA + (size_t)(m0 + row) * KK + k0 + c * 8);
        }
#pragma unroll
        for (int r = 0; r < 8; r++) {                // B: 1024 chunks
            int row = (tid + r * 128) >> 3;
            uint32_t soff = row * 128 + ((c ^ (row & 7)) << 4);
            CP_ASYNC16(sb + soff, gB + (size_t)(n0 + row) * KK + k0 + c * 8);
        }
    };

    // Prologue: fill STAGES-1 = 2 stages
#pragma unroll
    for (int p = 0; p < STAGES - 1; p++) {
        stage_load(p, p);
        CP_COMMIT();
    }

    float acc[4][8][4];
#pragma unroll
    for (int mi = 0; mi < 4; mi++)
#pragma unroll
        for (int ni = 0; ni < 8; ni++)
#pragma unroll
            for (int v = 0; v < 4; v++) acc[mi][ni][v] = 0.f;

    const int lrow  = lid & 15;          // row within 16-row subtile
    const int lhalf = lid >> 4;          // k-chunk half (0/1)
    const int lsw   = lrow & 7;          // swizzle key

    uint32_t aRow[4], bRow[4];
#pragma unroll
    for (int i = 0; i < 4; i++) {
        aRow[i] = (warpM + i * 16 + lrow) * 128;
        bRow[i] = (warpN + i * 16 + lrow) * 128;
    }

    for (int it = 0; it < K_ITERS; it++) {
        CP_WAIT1();
        __syncthreads();

        int ld = it + STAGES - 1;
        if (ld < K_ITERS) stage_load(ld % STAGES, ld);
        CP_COMMIT();

        const int st = it % STAGES;
        const uint32_t aBase = sbase + st * A_STAGE_BYTES;
        const uint32_t bBase = sbase + STAGES * A_STAGE_BYTES + st * B_STAGE_BYTES;

#pragma unroll
        for (int kt = 0; kt < 4; kt++) {
            const uint32_t off = (uint32_t)(((kt * 2 + lhalf) ^ lsw) << 4);
            uint32_t fa[4][4];
#pragma unroll
            for (int mi = 0; mi < 4; mi++)
                LDSM_X4(fa[mi], aBase + aRow[mi] + off);
            uint32_t fb[4][4];
#pragma unroll
            for (int np = 0; np < 4; np++)
                LDSM_X4(fb[np], bBase + bRow[np] + off);
#pragma unroll
            for (int mi = 0; mi < 4; mi++)
#pragma unroll
                for (int ni = 0; ni < 8; ni++) {
                    const int np = ni >> 1, h = ni & 1;
                    MMA16816(acc[mi][ni], fa[mi], fb[np][h], fb[np][2 + h]);
                }
        }
    }

    // Epilogue: direct fp32 stores (coalesced float2 per thread)
#pragma unroll
    for (int mi = 0; mi < 4; mi++) {
        int row = m0 + warpM + mi * 16 + (lid >> 2);
#pragma unroll
        for (int ni = 0; ni < 8; ni++) {
            int col = n0 + warpN + ni * 8 + (lid & 3) * 2;
            float2 v0 = make_float2(acc[mi][ni][0], acc[mi][ni][1]);
            float2 v1 = make_float2(acc[mi][ni][2], acc[mi][ni][3]);
            *reinterpret_cast<float2*>(C + (size_t)row * NN + col)       = v0;
            *reinterpret_cast<float2*>(C + (size_t)(row + 8) * NN + col) = v1;
        }
    }
}

// ---------------------------------------------------------------------------
// Host launch
// ---------------------------------------------------------------------------
extern "C" void kernel_launch(void* const* d_in, const int* in_sizes, int n_in,
                              void* d_out, int out_size) {
    const float* A  = (const float*)d_in[0];
    const int*   Bp = (const int*)d_in[1];
    const float* sc = (const float*)d_in[2];
    float* C = (float*)d_out;

    void* pAh = nullptr; void* pWh = nullptr;
    cudaGetSymbolAddress(&pAh, g_Ah);
    cudaGetSymbolAddress(&pWh, g_Wh);

    prep_a_kernel<<<(MM * (KK / 8)) / 256, 256>>>(A, (__half*)pAh);
    prep_w_kernel<<<dim3(NN / 256, (KK / 8) / 8), 256>>>(Bp, sc, (__half*)pWh);

    cudaFuncSetAttribute(gemm_kernel, cudaFuncAttributeMaxDynamicSharedMemorySize,
                         SMEM_BYTES);
    gemm_kernel<<<(MM / TM) * (NN / TN), 128, SMEM_BYTES>>>(
        (const __half*)pAh, (const __half*)pWh, C);
}

// round 6
// speedup vs baseline: 1.2194x; 1.2194x over previous
#include <cuda_runtime.h>
#include <cuda_fp16.h>
#include <cstdint>

// Problem constants
#define MM 8192
#define NN 8192
#define KK 4096
#define TM 128
#define TN 256
#define KS 64               // K elems per pipeline stage
#define STAGES 4
#define K_ITERS (KK / KS)   // 64
#define KTILES  (KK / 16)   // 256 k-tiles of 16

// Static scratch: A in mma-fragment layout (64 MB), W fp16 N-major (64 MB)
// A fragment layout: tile (tm, tk) of 16x16 -> 512 B block at (tm*KTILES + tk)*512,
// 32 lanes x 16 B, each 16B = {a0,a1,a2,a3} words in mma.m16n8k16 operand order.
__device__ uint4  g_Af[(size_t)MM * KK / 8];
__device__ __half g_Wh[(size_t)NN * KK];

// ---------------------------------------------------------------------------
// Prep kernel 1: A (fp32, MxK) -> fragment-layout fp16.
// One thread = one lane slot of one 16x16 tile (reads 4x float2, writes 16B).
// ---------------------------------------------------------------------------
__global__ void prep_a_kernel(const float* __restrict__ A, uint4* __restrict__ Af) {
    int t    = blockIdx.x * 256 + threadIdx.x;
    int lane = t & 31;
    int tile = t >> 5;
    int tk   = tile & (KTILES - 1);
    int tm   = tile >> 8;                // tile / KTILES
    int g    = lane >> 2;                // fragment group row (0..7)
    int tg   = lane & 3;                 // thread-in-group (col pair)
    const float* p0 = A + (size_t)(tm * 16 + g) * KK + tk * 16 + tg * 2;
    const float* p1 = p0 + 8 * KK;       // row +8
    float2 v00 = *reinterpret_cast<const float2*>(p0);       // a0: (g,   2t)
    float2 v10 = *reinterpret_cast<const float2*>(p1);       // a1: (g+8, 2t)
    float2 v01 = *reinterpret_cast<const float2*>(p0 + 8);   // a2: (g,   2t+8)
    float2 v11 = *reinterpret_cast<const float2*>(p1 + 8);   // a3: (g+8, 2t+8)
    union { __half2 h[4]; uint4 u; } out;
    out.h[0] = __floats2half2_rn(v00.x, v00.y);
    out.h[1] = __floats2half2_rn(v10.x, v10.y);
    out.h[2] = __floats2half2_rn(v01.x, v01.y);
    out.h[3] = __floats2half2_rn(v11.x, v11.y);
    Af[(size_t)tile * 32 + lane] = out.u;
}

// ---------------------------------------------------------------------------
// Prep kernel 2: dequant int4 -> Wh (fp16, N x K), N-major rows.
// One thread = one n column x 64 k (8 packed words, one scale group).
// ---------------------------------------------------------------------------
__global__ void prep_w_kernel(const int* __restrict__ Bp, const float* __restrict__ s,
                              __half* __restrict__ Wh) {
    int n   = blockIdx.x * 256 + threadIdx.x;
    int kp0 = blockIdx.y * 8;                         // 8 packed rows = 64 k
    float sv = s[(size_t)(kp0 >> 4) * NN + n];        // group = kp/16
    __half* dst = Wh + (size_t)n * KK + kp0 * 8;
#pragma unroll
    for (int r = 0; r < 8; r++) {
        int packed = Bp[(size_t)(kp0 + r) * NN + n];
        union { __half h[8]; uint4 u; } out;
#pragma unroll
        for (int j = 0; j < 8; j++) {
            int q = (packed >> (4 * j)) & 0xF;
            out.h[j] = __float2half((float)(q - 8) * sv);
        }
        *reinterpret_cast<uint4*>(dst + r * 8) = out.u;
    }
}

// ---------------------------------------------------------------------------
// GEMM: C = A @ W^T. CTA 128x256, 8 warps (2m x 4n), warp tile 64x64.
// A: fragment-layout global, LDG.128 per fragment via L1 (no smem).
// B: 4-stage cp.async pipeline in smem, LDSM; chunk swizzle c^(row&7).
// ---------------------------------------------------------------------------
#define B_STAGE_BYTES 32768              // 256 x 64 x 2
#define SMEM_BYTES (STAGES * B_STAGE_BYTES)   // 131072

__device__ __forceinline__ uint32_t smem_u32(const void* p) {
    uint32_t a;
    asm("{ .reg .u64 t; cvta.to.shared.u64 t, %1; cvt.u32.u64 %0, t; }" : "=r"(a) : "l"(p));
    return a;
}

#define CP_ASYNC16(smem, gmem) \
    asm volatile("cp.async.cg.shared.global [%0], [%1], 16;" :: "r"(smem), "l"(gmem))
#define CP_COMMIT() asm volatile("cp.async.commit_group;" ::: "memory")
#define CP_WAIT2()  asm volatile("cp.async.wait_group 2;" ::: "memory")

#define LDSM_X4(r, addr) \
    asm volatile("ldmatrix.sync.aligned.m8n8.x4.shared.b16 {%0,%1,%2,%3}, [%4];" \
        : "=r"((r)[0]), "=r"((r)[1]), "=r"((r)[2]), "=r"((r)[3]) : "r"(addr))

#define MMA16816(d, a, b0, b1) \
    asm volatile("mma.sync.aligned.m16n8k16.row.col.f32.f16.f16.f32 " \
        "{%0,%1,%2,%3}, {%4,%5,%6,%7}, {%8,%9}, {%0,%1,%2,%3};" \
        : "+f"((d)[0]), "+f"((d)[1]), "+f"((d)[2]), "+f"((d)[3]) \
        : "r"((a)[0]), "r"((a)[1]), "r"((a)[2]), "r"((a)[3]), "r"(b0), "r"(b1))

__global__ __launch_bounds__(256, 1) void gemm_kernel(
    const uint4* __restrict__ gAf,
    const __half* __restrict__ gB,
    float* __restrict__ C)
{
    extern __shared__ char smem[];
    const uint32_t sbase = smem_u32(smem);
    const int tid = threadIdx.x, wid = tid >> 5, lid = tid & 31;

    // CTA swizzle: 8-wide m-bands sweeping n (L2 reuse)
    const int TILES_N = NN / TN;        // 32
    const int GW = 8;
    int bid  = blockIdx.x;
    int band = bid / (GW * TILES_N);
    int rem  = bid % (GW * TILES_N);
    const int m0 = (band * GW + (rem % GW)) * TM;
    const int n0 = (rem / GW) * TN;

    const int warpM = (wid & 1) * 64;   // 2 m-warps
    const int warpN = (wid >> 1) * 64;  // 4 n-warps

    // A fragment pointers: tile (mt, kt16) at gAf[(mt*KTILES + kt16)*32 + lane]
    // Per warp: 4 m-tiles (mtBase..+3); advance kt16 0..255.
    const int mtBase = (m0 + warpM) >> 4;
    const uint4* aP[4];
#pragma unroll
    for (int i = 0; i < 4; i++)
        aP[i] = gAf + ((size_t)(mtBase + i) * KTILES) * 32 + lid;

    auto stage_load = [&](int st, int it) {
        const int k0 = it * KS;
        const uint32_t sb = sbase + st * B_STAGE_BYTES;
        const int c = tid & 7;
#pragma unroll
        for (int r = 0; r < 8; r++) {                // B: 2048 chunks / 256 thr
            int row = (tid + r * 256) >> 3;
            uint32_t soff = row * 128 + ((c ^ (row & 7)) << 4);
            CP_ASYNC16(sb + soff, gB + (size_t)(n0 + row) * KK + k0 + c * 8);
        }
    };

    // Prologue: fill STAGES-1 stages
#pragma unroll
    for (int p = 0; p < STAGES - 1; p++) {
        stage_load(p, p);
        CP_COMMIT();
    }

    float acc[4][8][4];
#pragma unroll
    for (int mi = 0; mi < 4; mi++)
#pragma unroll
        for (int ni = 0; ni < 8; ni++)
#pragma unroll
            for (int v = 0; v < 4; v++) acc[mi][ni][v] = 0.f;

    const int lrow  = lid & 15;          // row within 16-row subtile
    const int lhalf = lid >> 4;          // k-chunk half (0/1)
    const int lsw   = lrow & 7;          // swizzle key

    uint32_t bRow[4];
#pragma unroll
    for (int i = 0; i < 4; i++)
        bRow[i] = (warpN + i * 16 + lrow) * 128;

    // A fragment double buffer; preload ktile 0
    uint4 fa[2][4];
#pragma unroll
    for (int i = 0; i < 4; i++) fa[0][i] = __ldg(aP[i]);

    for (int it = 0; it < K_ITERS; it++) {
        CP_WAIT2();
        __syncthreads();

        int ld = it + STAGES - 1;
        if (ld < K_ITERS) stage_load(ld % STAGES, ld);
        CP_COMMIT();

        const int st = it % STAGES;
        const uint32_t bBase = sbase + st * B_STAGE_BYTES;

#pragma unroll
        for (int kt = 0; kt < 4; kt++) {
            const int cur = kt & 1, nxt = cur ^ 1;
            const int ktile = it * 4 + kt;
            // Prefetch next ktile's A fragments (pure global; crosses it boundary)
            if (ktile + 1 < KTILES) {
#pragma unroll
                for (int i = 0; i < 4; i++)
                    fa[nxt][i] = __ldg(aP[i] + (size_t)(ktile + 1) * 32);
            }
            // B fragments for this kt
            const uint32_t off = (uint32_t)(((kt * 2 + lhalf) ^ lsw) << 4);
            uint32_t fb[4][4];
#pragma unroll
            for (int np = 0; np < 4; np++)
                LDSM_X4(fb[np], bBase + bRow[np] + off);
#pragma unroll
            for (int mi = 0; mi < 4; mi++) {
                const uint32_t* fam = reinterpret_cast<const uint32_t*>(&fa[cur][mi]);
#pragma unroll
                for (int ni = 0; ni < 8; ni++) {
                    const int np = ni >> 1, h = ni & 1;
                    MMA16816(acc[mi][ni], fam, fb[np][h], fb[np][2 + h]);
                }
            }
        }
    }

    // Epilogue: direct fp32 stores (coalesced float2 per thread)
#pragma unroll
    for (int mi = 0; mi < 4; mi++) {
        int row = m0 + warpM + mi * 16 + (lid >> 2);
#pragma unroll
        for (int ni = 0; ni < 8; ni++) {
            int col = n0 + warpN + ni * 8 + (lid & 3) * 2;
            float2 v0 = make_float2(acc[mi][ni][0], acc[mi][ni][1]);
            float2 v1 = make_float2(acc[mi][ni][2], acc[mi][ni][3]);
            *reinterpret_cast<float2*>(C + (size_t)row * NN + col)       = v0;
            *reinterpret_cast<float2*>(C + (size_t)(row + 8) * NN + col) = v1;
        }
    }
}

// ---------------------------------------------------------------------------
// Host launch
// ---------------------------------------------------------------------------
extern "C" void kernel_launch(void* const* d_in, const int* in_sizes, int n_in,
                              void* d_out, int out_size) {
    const float* A  = (const float*)d_in[0];
    const int*   Bp = (const int*)d_in[1];
    const float* sc = (const float*)d_in[2];
    float* C = (float*)d_out;

    void* pAf = nullptr; void* pWh = nullptr;
    cudaGetSymbolAddress(&pAf, g_Af);
    cudaGetSymbolAddress(&pWh, g_Wh);

    // (MM/16)*(KK/16) tiles * 32 lanes / 256 threads
    prep_a_kernel<<<(MM / 16) * (KK / 16) * 32 / 256, 256>>>(A, (uint4*)pAf);
    prep_w_kernel<<<dim3(NN / 256, (KK / 8) / 8), 256>>>(Bp, sc, (__half*)pWh);

    cudaFuncSetAttribute(gemm_kernel, cudaFuncAttributeMaxDynamicSharedMemorySize,
                         SMEM_BYTES);
    gemm_kernel<<<(MM / TM) * (NN / TN), 256, SMEM_BYTES>>>(
        (const uint4*)pAf, (const __half*)pWh, C);
}

// round 7
// speedup vs baseline: 1.4443x; 1.1845x over previous
#include <cuda_runtime.h>
#include <cuda_fp16.h>
#include <cstdint>

// Problem constants
#define MM 8192
#define NN 8192
#define KK 4096
#define TM 128
#define TN 256
#define KS 64               // K elems per pipeline stage (128B rows)
#define STAGES 4
#define K_ITERS (KK / KS)   // 64

// Static scratch (allocation-free rule: __device__ globals): 64 MB + 64 MB
__device__ __half g_Ah[(size_t)MM * KK];
__device__ __half g_Wh[(size_t)NN * KK];

// ---------------------------------------------------------------------------
// Fused prep kernel.
// Blocks [0, 16384): A (fp32 -> fp16), 8 elems/thread.
// Blocks [16384, 18432): W (int4 dequant -> fp16 N-major), 64 k per thread.
// ---------------------------------------------------------------------------
#define A_BLOCKS (MM * KK / 8 / 256)     // 16384
#define W_BLOCKS ((NN / 256) * ((KK / 8) / 8))   // 32 * 64 = 2048

__global__ void prep_kernel(const float* __restrict__ A, __half* __restrict__ Ah,
                            const int* __restrict__ Bp, const float* __restrict__ s,
                            __half* __restrict__ Wh) {
    int b = blockIdx.x;
    if (b < A_BLOCKS) {
        size_t base = ((size_t)b * 256 + threadIdx.x) * 8;
        float4 v0 = *reinterpret_cast<const float4*>(A + base);
        float4 v1 = *reinterpret_cast<const float4*>(A + base + 4);
        union { __half h[8]; uint4 u; } out;
        out.h[0] = __float2half(v0.x); out.h[1] = __float2half(v0.y);
        out.h[2] = __float2half(v0.z); out.h[3] = __float2half(v0.w);
        out.h[4] = __float2half(v1.x); out.h[5] = __float2half(v1.y);
        out.h[6] = __float2half(v1.z); out.h[7] = __float2half(v1.w);
        *reinterpret_cast<uint4*>(Ah + base) = out.u;
    } else {
        int bw  = b - A_BLOCKS;
        int n   = (bw & 31) * 256 + threadIdx.x;      // 32 x-blocks
        int kp0 = (bw >> 5) * 8;                      // 64 y-blocks, 8 packed rows
        float sv = s[(size_t)(kp0 >> 4) * NN + n];    // group = kp/16
        __half* dst = Wh + (size_t)n * KK + kp0 * 8;
#pragma unroll
        for (int r = 0; r < 8; r++) {
            int packed = Bp[(size_t)(kp0 + r) * NN + n];
            union { __half h[8]; uint4 u; } out;
#pragma unroll
            for (int j = 0; j < 8; j++) {
                int q = (packed >> (4 * j)) & 0xF;
                out.h[j] = __float2half((float)(q - 8) * sv);
            }
            *reinterpret_cast<uint4*>(dst + r * 8) = out.u;
        }
    }
}

// ---------------------------------------------------------------------------
// GEMM: C[M,N] = Ah @ Wh^T (fp16 in, f32 acc)
// CTA 128x256, 8 warps (2m x 4n), warp tile 64x64, mma.sync.m16n8k16.
// 4-stage cp.async pipeline, KS=64; chunk swizzle c^(row&7).
// cp.async issuance split across kt blocks; A-fragment prefetch (1 kt deep).
// ---------------------------------------------------------------------------
#define A_STAGE_BYTES 16384              // 128 x 64 x 2
#define B_STAGE_BYTES 32768              // 256 x 64 x 2
#define SMEM_BYTES (STAGES * (A_STAGE_BYTES + B_STAGE_BYTES))   // 196608

__device__ __forceinline__ uint32_t smem_u32(const void* p) {
    uint32_t a;
    asm("{ .reg .u64 t; cvta.to.shared.u64 t, %1; cvt.u32.u64 %0, t; }" : "=r"(a) : "l"(p));
    return a;
}

#define CP_ASYNC16(smem, gmem) \
    asm volatile("cp.async.cg.shared.global [%0], [%1], 16;" :: "r"(smem), "l"(gmem))
#define CP_COMMIT() asm volatile("cp.async.commit_group;" ::: "memory")
#define CP_WAIT2()  asm volatile("cp.async.wait_group 2;" ::: "memory")

#define LDSM_X4(r, addr) \
    asm volatile("ldmatrix.sync.aligned.m8n8.x4.shared.b16 {%0,%1,%2,%3}, [%4];" \
        : "=r"((r)[0]), "=r"((r)[1]), "=r"((r)[2]), "=r"((r)[3]) : "r"(addr))

#define MMA16816(d, a, b0, b1) \
    asm volatile("mma.sync.aligned.m16n8k16.row.col.f32.f16.f16.f32 " \
        "{%0,%1,%2,%3}, {%4,%5,%6,%7}, {%8,%9}, {%0,%1,%2,%3};" \
        : "+f"((d)[0]), "+f"((d)[1]), "+f"((d)[2]), "+f"((d)[3]) \
        : "r"((a)[0]), "r"((a)[1]), "r"((a)[2]), "r"((a)[3]), "r"(b0), "r"(b1))

__global__ __launch_bounds__(256, 1) void gemm_kernel(
    const __half* __restrict__ gA,
    const __half* __restrict__ gB,
    float* __restrict__ C)
{
    extern __shared__ char smem[];
    const uint32_t sbase = smem_u32(smem);
    const int tid = threadIdx.x, wid = tid >> 5, lid = tid & 31;

    // CTA swizzle: 8-wide m-bands sweeping n (L2 reuse)
    const int TILES_N = NN / TN;        // 32
    const int GW = 8;
    int bid  = blockIdx.x;
    int band = bid / (GW * TILES_N);
    int rem  = bid % (GW * TILES_N);
    const int m0 = (band * GW + (rem % GW)) * TM;
    const int n0 = (rem / GW) * TN;

    const int warpM = (wid & 1) * 64;   // 2 m-warps
    const int warpN = (wid >> 1) * 64;  // 4 n-warps

    // Quarter stage load: q in [0,4): A chunk r=q, B chunks r=2q,2q+1
    const int cchk = tid & 7;
    auto stage_load_part = [&](int st, int it, int q) {
        const int k0 = it * KS;
        const uint32_t sa = sbase + st * A_STAGE_BYTES;
        const uint32_t sb = sbase + STAGES * A_STAGE_BYTES + st * B_STAGE_BYTES;
        {
            int row = (tid + q * 256) >> 3;
            uint32_t soff = row * 128 + ((cchk ^ (row & 7)) << 4);
            CP_ASYNC16(sa + soff, gA + (size_t)(m0 + row) * KK + k0 + cchk * 8);
        }
#pragma unroll
        for (int r = 2 * q; r < 2 * q + 2; r++) {
            int row = (tid + r * 256) >> 3;
            uint32_t soff = row * 128 + ((cchk ^ (row & 7)) << 4);
            CP_ASYNC16(sb + soff, gB + (size_t)(n0 + row) * KK + k0 + cchk * 8);
        }
    };

    // Prologue: fill STAGES-1 stages
#pragma unroll
    for (int p = 0; p < STAGES - 1; p++) {
#pragma unroll
        for (int q = 0; q < 4; q++) stage_load_part(p, p, q);
        CP_COMMIT();
    }

    float acc[4][8][4];
#pragma unroll
    for (int mi = 0; mi < 4; mi++)
#pragma unroll
        for (int ni = 0; ni < 8; ni++)
#pragma unroll
            for (int v = 0; v < 4; v++) acc[mi][ni][v] = 0.f;

    const int lrow  = lid & 15;          // row within 16-row subtile
    const int lhalf = lid >> 4;          // k-chunk half (0/1)
    const int lsw   = lrow & 7;          // swizzle key

    uint32_t aRow[4], bRow[4];
#pragma unroll
    for (int i = 0; i < 4; i++) {
        aRow[i] = (warpM + i * 16 + lrow) * 128;
        bRow[i] = (warpN + i * 16 + lrow) * 128;
    }

    for (int it = 0; it < K_ITERS; it++) {
        CP_WAIT2();
        __syncthreads();

        const int st = it % STAGES;
        const int ld = it + STAGES - 1;
        const int ldst = ld % STAGES;
        const bool doLoad = (ld < K_ITERS);
        const uint32_t aBase = sbase + st * A_STAGE_BYTES;
        const uint32_t bBase = sbase + STAGES * A_STAGE_BYTES + st * B_STAGE_BYTES;

        uint32_t fa[2][4][4];
        // A head: kt=0 fragments
        {
            const uint32_t off = (uint32_t)((lhalf ^ lsw) << 4);
#pragma unroll
            for (int i = 0; i < 4; i++) LDSM_X4(fa[0][i], aBase + aRow[i] + off);
        }

#pragma unroll
        for (int kt = 0; kt < 4; kt++) {
            const int cur = kt & 1, nxt = cur ^ 1;
            const uint32_t off = (uint32_t)(((kt * 2 + lhalf) ^ lsw) << 4);
            // B fragments for this kt
            uint32_t fb[4][4];
#pragma unroll
            for (int np = 0; np < 4; np++)
                LDSM_X4(fb[np], bBase + bRow[np] + off);
            // Prefetch next kt's A fragments
            if (kt < 3) {
                const uint32_t offn = (uint32_t)((((kt + 1) * 2 + lhalf) ^ lsw) << 4);
#pragma unroll
                for (int i = 0; i < 4; i++)
                    LDSM_X4(fa[nxt][i], aBase + aRow[i] + offn);
            }
            // One quarter of the next stage's cp.asyncs
            if (doLoad) stage_load_part(ldst, ld, kt);
            if (kt == 3) { CP_COMMIT(); }
            // MMA block
#pragma unroll
            for (int mi = 0; mi < 4; mi++)
#pragma unroll
                for (int ni = 0; ni < 8; ni++) {
                    const int np = ni >> 1, h = ni & 1;
                    MMA16816(acc[mi][ni], fa[cur][mi], fb[np][h], fb[np][2 + h]);
                }
        }
    }

    // Epilogue: direct fp32 stores (coalesced float2 per thread)
#pragma unroll
    for (int mi = 0; mi < 4; mi++) {
        int row = m0 + warpM + mi * 16 + (lid >> 2);
#pragma unroll
        for (int ni = 0; ni < 8; ni++) {
            int col = n0 + warpN + ni * 8 + (lid & 3) * 2;
            float2 v0 = make_float2(acc[mi][ni][0], acc[mi][ni][1]);
            float2 v1 = make_float2(acc[mi][ni][2], acc[mi][ni][3]);
            *reinterpret_cast<float2*>(C + (size_t)row * NN + col)       = v0;
            *reinterpret_cast<float2*>(C + (size_t)(row + 8) * NN + col) = v1;
        }
    }
}

// ---------------------------------------------------------------------------
// Host launch
// ---------------------------------------------------------------------------
extern "C" void kernel_launch(void* const* d_in, const int* in_sizes, int n_in,
                              void* d_out, int out_size) {
    const float* A  = (const float*)d_in[0];
    const int*   Bp = (const int*)d_in[1];
    const float* sc = (const float*)d_in[2];
    float* C = (float*)d_out;

    void* pAh = nullptr; void* pWh = nullptr;
    cudaGetSymbolAddress(&pAh, g_Ah);
    cudaGetSymbolAddress(&pWh, g_Wh);

    prep_kernel<<<A_BLOCKS + W_BLOCKS, 256>>>(A, (__half*)pAh, Bp, sc, (__half*)pWh);

    cudaFuncSetAttribute(gemm_kernel, cudaFuncAttributeMaxDynamicSharedMemorySize,
                         SMEM_BYTES);
    gemm_kernel<<<(MM / TM) * (NN / TN), 256, SMEM_BYTES>>>(
        (const __half*)pAh, (const __half*)pWh, C);
}

// round 8
// speedup vs baseline: 1.4987x; 1.0377x over previous
#include <cuda_runtime.h>
#include <cuda_fp16.h>
#include <cstdint>

// Problem constants
#define MM 8192
#define NN 8192
#define KK 4096
#define TM 128
#define TN 256
#define KS 64               // K elems per pipeline stage (128B rows)
#define STAGES 4
#define K_ITERS (KK / KS)   // 64

// Static scratch (allocation-free rule: __device__ globals): 64 MB + 64 MB
__device__ __half g_Ah[(size_t)MM * KK];
__device__ __half g_Wh[(size_t)NN * KK];

// ---------------------------------------------------------------------------
// Fused prep kernel.
// Blocks [0, A_BLOCKS): A (fp32 -> fp16), 8 elems/thread.
// Blocks [A_BLOCKS, +W_BLOCKS): W (int4 dequant -> fp16 N-major), 64 k/thread.
// ---------------------------------------------------------------------------
#define A_BLOCKS (MM * KK / 8 / 256)             // 16384
#define W_BLOCKS ((NN / 256) * ((KK / 8) / 8))   // 2048

__global__ void prep_kernel(const float* __restrict__ A, __half* __restrict__ Ah,
                            const int* __restrict__ Bp, const float* __restrict__ s,
                            __half* __restrict__ Wh) {
    int b = blockIdx.x;
    if (b < A_BLOCKS) {
        size_t base = ((size_t)b * 256 + threadIdx.x) * 8;
        float4 v0 = *reinterpret_cast<const float4*>(A + base);
        float4 v1 = *reinterpret_cast<const float4*>(A + base + 4);
        union { __half h[8]; uint4 u; } out;
        out.h[0] = __float2half(v0.x); out.h[1] = __float2half(v0.y);
        out.h[2] = __float2half(v0.z); out.h[3] = __float2half(v0.w);
        out.h[4] = __float2half(v1.x); out.h[5] = __float2half(v1.y);
        out.h[6] = __float2half(v1.z); out.h[7] = __float2half(v1.w);
        *reinterpret_cast<uint4*>(Ah + base) = out.u;
    } else {
        int bw  = b - A_BLOCKS;
        int n   = (bw & 31) * 256 + threadIdx.x;      // 32 x-blocks
        int kp0 = (bw >> 5) * 8;                      // 8 packed rows = 64 k
        float sv = s[(size_t)(kp0 >> 4) * NN + n];    // group = kp/16
        __half* dst = Wh + (size_t)n * KK + kp0 * 8;
#pragma unroll
        for (int r = 0; r < 8; r++) {
            int packed = Bp[(size_t)(kp0 + r) * NN + n];
            union { __half h[8]; uint4 u; } out;
#pragma unroll
            for (int j = 0; j < 8; j++) {
                int q = (packed >> (4 * j)) & 0xF;
                out.h[j] = __float2half((float)(q - 8) * sv);
            }
            *reinterpret_cast<uint4*>(dst + r * 8) = out.u;
        }
    }
}

// ---------------------------------------------------------------------------
// GEMM: C[M,N] = Ah @ Wh^T (fp16 in, f32 acc)
// CTA 128x256, 512 threads, 16 warps (2m x 8n), warp tile 64x32.
// 4-stage cp.async pipeline, KS=64; chunk swizzle c^(row&7).
// Persistent cp.async pointers (advance +128B/it); loads spread across kt.
// ---------------------------------------------------------------------------
#define A_STAGE_BYTES 16384              // 128 x 64 x 2
#define B_STAGE_BYTES 32768              // 256 x 64 x 2
#define SMEM_BYTES (STAGES * (A_STAGE_BYTES + B_STAGE_BYTES))   // 196608
#define B_REGION (STAGES * A_STAGE_BYTES)                       // 65536

__device__ __forceinline__ uint32_t smem_u32(const void* p) {
    uint32_t a;
    asm("{ .reg .u64 t; cvta.to.shared.u64 t, %1; cvt.u32.u64 %0, t; }" : "=r"(a) : "l"(p));
    return a;
}

#define CP_ASYNC16(smem, gmem) \
    asm volatile("cp.async.cg.shared.global [%0], [%1], 16;" :: "r"(smem), "l"(gmem))
#define CP_COMMIT() asm volatile("cp.async.commit_group;" ::: "memory")
#define CP_WAIT2()  asm volatile("cp.async.wait_group 2;" ::: "memory")

#define LDSM_X4(r, addr) \
    asm volatile("ldmatrix.sync.aligned.m8n8.x4.shared.b16 {%0,%1,%2,%3}, [%4];" \
        : "=r"((r)[0]), "=r"((r)[1]), "=r"((r)[2]), "=r"((r)[3]) : "r"(addr))

#define MMA16816(d, a, b0, b1) \
    asm volatile("mma.sync.aligned.m16n8k16.row.col.f32.f16.f16.f32 " \
        "{%0,%1,%2,%3}, {%4,%5,%6,%7}, {%8,%9}, {%0,%1,%2,%3};" \
        : "+f"((d)[0]), "+f"((d)[1]), "+f"((d)[2]), "+f"((d)[3]) \
        : "r"((a)[0]), "r"((a)[1]), "r"((a)[2]), "r"((a)[3]), "r"(b0), "r"(b1))

__global__ __launch_bounds__(512, 1) void gemm_kernel(
    const __half* __restrict__ gA,
    const __half* __restrict__ gB,
    float* __restrict__ C)
{
    extern __shared__ char smem[];
    const uint32_t sbase = smem_u32(smem);
    const int tid = threadIdx.x, wid = tid >> 5, lid = tid & 31;

    // CTA swizzle: 8-wide m-bands sweeping n (L2 reuse)
    const int TILES_N = NN / TN;        // 32
    const int GW = 8;
    int bid  = blockIdx.x;
    int band = bid / (GW * TILES_N);
    int rem  = bid % (GW * TILES_N);
    const int m0 = (band * GW + (rem % GW)) * TM;
    const int n0 = (rem / GW) * TN;

    const int warpM = (wid & 1) * 64;   // 2 m-warps
    const int warpN = (wid >> 1) * 32;  // 8 n-warps

    // --- cp.async persistent pointers: A 2 chunks/thread, B 4 chunks/thread ---
    // chunk i: row = i>>3, c = i&7; smem offset = row*128 + ((c ^ (row&7))<<4)
    const int cchk = tid & 7;
    uint64_t pA[2]; uint32_t oA[2];
    uint64_t pB[4]; uint32_t oB[4];
#pragma unroll
    for (int r = 0; r < 2; r++) {
        int row = (tid + r * 512) >> 3;
        oA[r] = row * 128 + ((cchk ^ (row & 7)) << 4);
        pA[r] = (uint64_t)(gA + (size_t)(m0 + row) * KK + cchk * 8);
    }
#pragma unroll
    for (int r = 0; r < 4; r++) {
        int row = (tid + r * 512) >> 3;
        oB[r] = row * 128 + ((cchk ^ (row & 7)) << 4);
        pB[r] = (uint64_t)(gB + (size_t)(n0 + row) * KK + cchk * 8);
    }

    auto load_full = [&](int st) {
        const uint32_t sa = sbase + st * A_STAGE_BYTES;
        const uint32_t sb = sbase + B_REGION + st * B_STAGE_BYTES;
#pragma unroll
        for (int r = 0; r < 2; r++) { CP_ASYNC16(sa + oA[r], (const void*)pA[r]); pA[r] += 128; }
#pragma unroll
        for (int r = 0; r < 4; r++) { CP_ASYNC16(sb + oB[r], (const void*)pB[r]); pB[r] += 128; }
    };

    // Prologue: fill STAGES-1 stages
#pragma unroll
    for (int p = 0; p < STAGES - 1; p++) {
        load_full(p);
        CP_COMMIT();
    }

    float acc[4][4][4];
#pragma unroll
    for (int mi = 0; mi < 4; mi++)
#pragma unroll
        for (int ni = 0; ni < 4; ni++)
#pragma unroll
            for (int v = 0; v < 4; v++) acc[mi][ni][v] = 0.f;

    const int lrow  = lid & 15;          // row within 16-row subtile
    const int lhalf = lid >> 4;          // k-chunk half (0/1)
    const int lsw   = lrow & 7;          // swizzle key

    uint32_t aRow[4], bRow[2];
#pragma unroll
    for (int i = 0; i < 4; i++) aRow[i] = (warpM + i * 16 + lrow) * 128;
#pragma unroll
    for (int i = 0; i < 2; i++) bRow[i] = (warpN + i * 16 + lrow) * 128;

    for (int it = 0; it < K_ITERS; it++) {
        CP_WAIT2();
        __syncthreads();

        const int st = it % STAGES;
        const int ldst = (it + STAGES - 1) % STAGES;
        const bool doLoad = (it + STAGES - 1 < K_ITERS);
        const uint32_t aBase = sbase + st * A_STAGE_BYTES;
        const uint32_t bBase = sbase + B_REGION + st * B_STAGE_BYTES;
        const uint32_t lsa = sbase + ldst * A_STAGE_BYTES;
        const uint32_t lsb = sbase + B_REGION + ldst * B_STAGE_BYTES;

#pragma unroll
        for (int kt = 0; kt < 4; kt++) {
            const uint32_t off = (uint32_t)(((kt * 2 + lhalf) ^ lsw) << 4);
            uint32_t fb[2][4];
#pragma unroll
            for (int np = 0; np < 2; np++)
                LDSM_X4(fb[np], bBase + bRow[np] + off);
            uint32_t fa[4][4];
#pragma unroll
            for (int mi = 0; mi < 4; mi++)
                LDSM_X4(fa[mi], aBase + aRow[mi] + off);
            // Spread next-stage cp.asyncs across kt slots
            if (doLoad) {
                if (kt == 0) {
                    CP_ASYNC16(lsa + oA[0], (const void*)pA[0]); pA[0] += 128;
                    CP_ASYNC16(lsb + oB[0], (const void*)pB[0]); pB[0] += 128;
                } else if (kt == 1) {
                    CP_ASYNC16(lsa + oA[1], (const void*)pA[1]); pA[1] += 128;
                    CP_ASYNC16(lsb + oB[1], (const void*)pB[1]); pB[1] += 128;
                } else if (kt == 2) {
                    CP_ASYNC16(lsb + oB[2], (const void*)pB[2]); pB[2] += 128;
                } else {
                    CP_ASYNC16(lsb + oB[3], (const void*)pB[3]); pB[3] += 128;
                }
            }
            if (kt == 3) { CP_COMMIT(); }
#pragma unroll
            for (int mi = 0; mi < 4; mi++)
#pragma unroll
                for (int ni = 0; ni < 4; ni++) {
                    const int np = ni >> 1, h = ni & 1;
                    MMA16816(acc[mi][ni], fa[mi], fb[np][h], fb[np][2 + h]);
                }
        }
    }

    // Epilogue: direct fp32 stores (coalesced float2 per thread)
#pragma unroll
    for (int mi = 0; mi < 4; mi++) {
        int row = m0 + warpM + mi * 16 + (lid >> 2);
#pragma unroll
        for (int ni = 0; ni < 4; ni++) {
            int col = n0 + warpN + ni * 8 + (lid & 3) * 2;
            float2 v0 = make_float2(acc[mi][ni][0], acc[mi][ni][1]);
            float2 v1 = make_float2(acc[mi][ni][2], acc[mi][ni][3]);
            *reinterpret_cast<float2*>(C + (size_t)row * NN + col)       = v0;
            *reinterpret_cast<float2*>(C + (size_t)(row + 8) * NN + col) = v1;
        }
    }
}

// ---------------------------------------------------------------------------
// Host launch
// ---------------------------------------------------------------------------
extern "C" void kernel_launch(void* const* d_in, const int* in_sizes, int n_in,
                              void* d_out, int out_size) {
    const float* A  = (const float*)d_in[0];
    const int*   Bp = (const int*)d_in[1];
    const float* sc = (const float*)d_in[2];
    float* C = (float*)d_out;

    void* pAh = nullptr; void* pWh = nullptr;
    cudaGetSymbolAddress(&pAh, g_Ah);
    cudaGetSymbolAddress(&pWh, g_Wh);

    prep_kernel<<<A_BLOCKS + W_BLOCKS, 256>>>(A, (__half*)pAh, Bp, sc, (__half*)pWh);

    cudaFuncSetAttribute(gemm_kernel, cudaFuncAttributeMaxDynamicSharedMemorySize,
                         SMEM_BYTES);
    gemm_kernel<<<(MM / TM) * (NN / TN), 512, SMEM_BYTES>>>(
        (const __half*)pAh, (const __half*)pWh, C);
}